// round 17
// baseline (speedup 1.0000x reference)
#include <cuda_runtime.h>
#include <cuda_bf16.h>
#include <cstdint>

#define EPS 1e-7f
#define BB 16
#define LL 1024
#define DD 256
#define PP 20

#define SW128(o) ((o) ^ (((o) >> 3) & 0x70))

__device__ __forceinline__ uint32_t s2u(const void* p) {
    uint32_t a;
    asm("{ .reg .u64 t; cvta.to.shared.u64 t, %1; cvt.u32.u64 %0, t; }"
        : "=r"(a) : "l"(p));
    return a;
}

__device__ __forceinline__ void ldm_x4(uint32_t* r, uint32_t addr) {
    asm volatile("ldmatrix.sync.aligned.m8n8.x4.shared.b16 {%0,%1,%2,%3}, [%4];"
                 : "=r"(r[0]), "=r"(r[1]), "=r"(r[2]), "=r"(r[3]) : "r"(addr));
}

__device__ __forceinline__ void mma_bf16(float* c, const uint32_t* a, const uint32_t* b) {
    asm volatile(
        "mma.sync.aligned.m16n8k16.row.col.f32.bf16.bf16.f32 "
        "{%0,%1,%2,%3}, {%4,%5,%6,%7}, {%8,%9}, {%0,%1,%2,%3};"
        : "+f"(c[0]), "+f"(c[1]), "+f"(c[2]), "+f"(c[3])
        : "r"(a[0]), "r"(a[1]), "r"(a[2]), "r"(a[3]), "r"(b[0]), "r"(b[1]));
}

__device__ __forceinline__ void cp16(uint32_t dst, const void* src) {
    asm volatile("cp.async.cg.shared.global [%0], [%1], 16;" :: "r"(dst), "l"(src));
}
#define CP_COMMIT asm volatile("cp.async.commit_group;" ::: "memory")
#define CP_WAIT1  asm volatile("cp.async.wait_group 1;" ::: "memory")
#define CP_WAIT0  asm volatile("cp.async.wait_group 0;" ::: "memory")

// packed fp32x2 helpers
#define FMA2(acc, a, b) \
    asm("fma.rn.f32x2 %0, %1, %2, %0;" : "+l"(acc) : "l"(a), "l"(b))
__device__ __forceinline__ unsigned long long pack2(float lo, float hi) {
    unsigned long long d;
    asm("mov.b64 %0, {%1, %2};" : "=l"(d) : "r"(__float_as_uint(lo)), "r"(__float_as_uint(hi)));
    return d;
}
__device__ __forceinline__ float lo32(unsigned long long u) { return __uint_as_float((unsigned)u); }
__device__ __forceinline__ float hi32(unsigned long long u) { return __uint_as_float((unsigned)(u >> 32)); }

// ======================= scratch =======================
__device__ float g_vp[BB*DD*32];       // v partials, [(b*DD+d)*32 + mt]
__device__ float g_v[BB*DD];
__device__ float g_w[BB*LL*DD];
__device__ __nv_bfloat16 g_zH[BB*DD*LL], g_zL[BB*DD*LL];       // z^T  [b][d][m]
__device__ __nv_bfloat16 g_x1h[BB*LL*DD], g_x1l[BB*LL*DD];     // [b][l][d]
__device__ __nv_bfloat16 g_Mh[BB*DD*DD],  g_Ml[BB*DD*DD];      // [b][i][j]

// ======== K0: MERGED s1-prep + s2-trans (blockIdx branch) ========
__global__ __launch_bounds__(256) void k_pt(const float* __restrict__ s1,
                                            const float* __restrict__ s2) {
    __shared__ float tile[32][257];
    __shared__ float sInvF[32];
    __shared__ float sInvW[32];
    int bid = blockIdx.x;
    int tid = threadIdx.x, lane = tid & 31, w = tid >> 5;

    if (bid < 2048) {
        int row = (bid * 256 + tid) >> 5;
        const float4* p = reinterpret_cast<const float4*>(s1) + (size_t)row * 64;
        float4 a = p[lane * 2], b = p[lane * 2 + 1];
        float ss = a.x*a.x + a.y*a.y + a.z*a.z + a.w*a.w
                 + b.x*b.x + b.y*b.y + b.z*b.z + b.w*b.w;
#pragma unroll
        for (int o = 16; o; o >>= 1) ss += __shfl_xor_sync(0xffffffffu, ss, o);
        float inv = rsqrtf(fmaxf(ss, EPS));
        float x[8] = {a.x*inv, a.y*inv, a.z*inv, a.w*inv,
                      b.x*inv, b.y*inv, b.z*inv, b.w*inv};
        __nv_bfloat16 h[8], l[8];
#pragma unroll
        for (int i = 0; i < 8; i++) {
            h[i] = __float2bfloat16(x[i]);
            l[i] = __float2bfloat16(x[i] - __bfloat162float(h[i]));
        }
        int o16 = row * 32 + lane;
        __nv_bfloat162 hh[4] = {{h[0],h[1]},{h[2],h[3]},{h[4],h[5]},{h[6],h[7]}};
        __nv_bfloat162 ll[4] = {{l[0],l[1]},{l[2],l[3]},{l[4],l[5]},{l[6],l[7]}};
        reinterpret_cast<uint4*>(g_x1h)[o16] = *reinterpret_cast<uint4*>(hh);
        reinterpret_cast<uint4*>(g_x1l)[o16] = *reinterpret_cast<uint4*>(ll);
        return;
    }

    int r = bid - 2048;
    int b = r >> 5, mt = r & 31;
    const float* src = s2 + ((size_t)(b * LL + mt * 32)) * DD;

#pragma unroll
    for (int rr = 0; rr < 4; rr++) {
        int row = w * 4 + rr;
        const float4* p = reinterpret_cast<const float4*>(src + (size_t)row * DD);
        float4 a = p[lane * 2], bb = p[lane * 2 + 1];
        float* t = &tile[row][lane * 8];
        t[0]=a.x; t[1]=a.y; t[2]=a.z; t[3]=a.w;
        t[4]=bb.x; t[5]=bb.y; t[6]=bb.z; t[7]=bb.w;
        float ss = a.x*a.x + a.y*a.y + a.z*a.z + a.w*a.w
                 + bb.x*bb.x + bb.y*bb.y + bb.z*bb.z + bb.w*bb.w;
#pragma unroll
        for (int o = 16; o; o >>= 1) ss += __shfl_xor_sync(0xffffffffu, ss, o);
        if (lane == 0) {
            float inv = rsqrtf(fmaxf(ss, EPS));
            sInvF[row] = inv;
            sInvW[row] = sqrtf(inv);
        }
    }
    __syncthreads();

    {
        float acc = 0.f;
#pragma unroll 8
        for (int m = 0; m < 32; m++) acc += tile[m][tid] * sInvF[m];
        g_vp[((size_t)(b * DD + tid)) * 32 + mt] = acc;
    }

    int p2  = (tid & 15) * 2;
    int dof = tid >> 4;
#pragma unroll
    for (int it = 0; it < 16; it++) {
        int d = it * 16 + dof;
        float v0 = tile[p2][d],     v1 = tile[p2 + 1][d];
        float z0 = v0 * sInvW[p2],  z1 = v1 * sInvW[p2 + 1];
        __nv_bfloat16 h0 = __float2bfloat16(z0);
        __nv_bfloat16 h1 = __float2bfloat16(z1);
        __nv_bfloat16 l0 = __float2bfloat16(z0 - __bfloat162float(h0));
        __nv_bfloat16 l1 = __float2bfloat16(z1 - __bfloat162float(h1));
        size_t o = ((size_t)(b * DD + d)) * LL + mt * 32 + p2;
        *reinterpret_cast<__nv_bfloat162*>(g_zH + o) = {h0, h1};
        *reinterpret_cast<__nv_bfloat162*>(g_zL + o) = {l0, l1};
    }
}

// ============ staging for GEMMs (A 128x64, B 64x64, hi+lo) ===================
#define SM_AH 0
#define SM_AL 16384
#define SM_BH 32768
#define SM_BL 40960
#define BUFSZ 49152

__device__ __forceinline__ void stage_tile(
    uint32_t sb,
    const __nv_bfloat16* __restrict__ aH, const __nv_bfloat16* __restrict__ aL,
    const __nv_bfloat16* __restrict__ bH, const __nv_bfloat16* __restrict__ bL,
    int lda, int ldb, int kc, int tid)
{
#pragma unroll
    for (int q = 0; q < 4; q++) {
        int idx = tid + q * 256;
        int row = idx >> 3, c = idx & 7;
        size_t go = (size_t)row * lda + (size_t)kc * 64 + c * 8;
        uint32_t so = SW128((uint32_t)(row * 128 + c * 16));
        cp16(sb + SM_AH + so, aH + go);
        cp16(sb + SM_AL + so, aL + go);
    }
#pragma unroll
    for (int q = 0; q < 2; q++) {
        int idx = tid + q * 256;
        int row = idx >> 3, c = idx & 7;
        size_t go = (size_t)row * ldb + (size_t)kc * 64 + c * 8;
        uint32_t so = SW128((uint32_t)(row * 128 + c * 16));
        cp16(sb + SM_BH + so, bH + go);
        cp16(sb + SM_BL + so, bL + go);
    }
}

// ======== K1: MERGED gram MMA (128 blocks) + v reduce (16 blocks) ========
__global__ __launch_bounds__(256) void k_gramv() {
    extern __shared__ __align__(128) char sm[];
    int bid = blockIdx.x;
    int tid = threadIdx.x;
    int lane = tid & 31, wid = tid >> 5;

    if (bid >= 128) {
        int base = (bid - 128) * 256 + wid * 32;
        for (int q = 0; q < 32; q++) {
            int gw = base + q;
            float v = g_vp[(size_t)gw * 32 + lane];
#pragma unroll
            for (int o = 16; o; o >>= 1) v += __shfl_xor_sync(0xffffffffu, v, o);
            if (lane == 0) g_v[gw] = v;
        }
        return;
    }

    uint32_t sb = s2u(sm);
    int b = bid & 15, it = (bid >> 4) & 1, jt = bid >> 5;
    const __nv_bfloat16* aH = g_zH + ((size_t)(b * DD + it * 128)) * LL;
    const __nv_bfloat16* aL = g_zL + ((size_t)(b * DD + it * 128)) * LL;
    const __nv_bfloat16* bH = g_zH + ((size_t)(b * DD + jt * 64)) * LL;
    const __nv_bfloat16* bL = g_zL + ((size_t)(b * DD + jt * 64)) * LL;

    int m0 = (wid & 3) * 32;
    int n0 = (wid >> 2) * 32;

    float acc[2][4][4];
#pragma unroll
    for (int mi = 0; mi < 2; mi++)
#pragma unroll
        for (int ni = 0; ni < 4; ni++)
#pragma unroll
            for (int q = 0; q < 4; q++) acc[mi][ni][q] = 0.f;

    uint32_t aoff[2], boff[2];
#pragma unroll
    for (int mi = 0; mi < 2; mi++) {
        int row = m0 + mi*16 + (lane & 15);
        aoff[mi] = SW128((uint32_t)(row * 128 + (lane >> 4) * 16));
    }
#pragma unroll
    for (int np = 0; np < 2; np++) {
        int row = n0 + np*16 + (lane & 7) + ((lane >> 4) << 3);
        boff[np] = SW128((uint32_t)(row * 128 + ((lane >> 3) & 1) * 16));
    }

    stage_tile(sb, aH, aL, bH, bL, LL, LL, 0, tid);
    CP_COMMIT;

    for (int kc = 0; kc < 16; kc++) {
        if (kc + 1 < 16) {
            stage_tile(sb + ((kc + 1) & 1) * BUFSZ, aH, aL, bH, bL, LL, LL, kc + 1, tid);
            CP_COMMIT;
            CP_WAIT1;
        } else {
            CP_WAIT0;
        }
        __syncthreads();

        uint32_t sbuf = sb + (kc & 1) * BUFSZ;
#pragma unroll
        for (int ks = 0; ks < 4; ks++) {
            uint32_t kb = ks * 32;
            uint32_t ah[2][4], al[2][4], bh[2][4], bl[2][4];
#pragma unroll
            for (int mi = 0; mi < 2; mi++) {
                ldm_x4(ah[mi], sbuf + SM_AH + (aoff[mi] ^ kb));
                ldm_x4(al[mi], sbuf + SM_AL + (aoff[mi] ^ kb));
            }
#pragma unroll
            for (int np = 0; np < 2; np++) {
                ldm_x4(bh[np], sbuf + SM_BH + (boff[np] ^ kb));
                ldm_x4(bl[np], sbuf + SM_BL + (boff[np] ^ kb));
            }
#pragma unroll
            for (int mi = 0; mi < 2; mi++)
#pragma unroll
                for (int ni = 0; ni < 4; ni++) {
                    const uint32_t* bph = &bh[ni >> 1][(ni & 1) * 2];
                    const uint32_t* bpl = &bl[ni >> 1][(ni & 1) * 2];
                    mma_bf16(acc[mi][ni], ah[mi], bph);
                    mma_bf16(acc[mi][ni], ah[mi], bpl);
                    mma_bf16(acc[mi][ni], al[mi], bph);
                }
        }
        __syncthreads();
    }

#pragma unroll
    for (int mi = 0; mi < 2; mi++)
#pragma unroll
        for (int ni = 0; ni < 4; ni++) {
            int i = it * 128 + m0 + mi * 16 + (lane >> 2);
            int j = jt * 64 + n0 + ni * 8 + (lane & 3) * 2;
#pragma unroll
            for (int h = 0; h < 2; h++) {
                float v0 = acc[mi][ni][h*2], v1 = acc[mi][ni][h*2+1];
                size_t o = ((size_t)(b * DD + i + h * 8)) * DD + j;
                __nv_bfloat16 h0 = __float2bfloat16(v0);
                __nv_bfloat16 h1 = __float2bfloat16(v1);
                *reinterpret_cast<__nv_bfloat162*>(&g_Mh[o]) = {h0, h1};
                *reinterpret_cast<__nv_bfloat162*>(&g_Ml[o]) = {
                    __float2bfloat16(v0 - __bfloat162float(h0)),
                    __float2bfloat16(v1 - __bfloat162float(h1))};
            }
        }
}

// ======== K2: weighted GEMM: W[b][l][j] = sum_k x1[l][k]*M[j][k]; K=256 ====
__global__ __launch_bounds__(256) void k_wt_mma() {
    extern __shared__ __align__(128) char sm[];
    uint32_t sb = s2u(sm);
    int b = blockIdx.x, lt = blockIdx.y, jt = blockIdx.z;
    const __nv_bfloat16* aH = g_x1h + ((size_t)(b * LL + lt * 128)) * DD;
    const __nv_bfloat16* aL = g_x1l + ((size_t)(b * LL + lt * 128)) * DD;
    const __nv_bfloat16* bH = g_Mh + ((size_t)(b * DD + jt * 64)) * DD;
    const __nv_bfloat16* bL = g_Ml + ((size_t)(b * DD + jt * 64)) * DD;

    int tid = threadIdx.x;
    int lane = tid & 31, wid = tid >> 5;
    int m0 = (wid & 3) * 32;
    int n0 = (wid >> 2) * 32;

    float acc[2][4][4];
#pragma unroll
    for (int mi = 0; mi < 2; mi++)
#pragma unroll
        for (int ni = 0; ni < 4; ni++)
#pragma unroll
            for (int q = 0; q < 4; q++) acc[mi][ni][q] = 0.f;

    uint32_t aoff[2], boff[2];
#pragma unroll
    for (int mi = 0; mi < 2; mi++) {
        int row = m0 + mi*16 + (lane & 15);
        aoff[mi] = SW128((uint32_t)(row * 128 + (lane >> 4) * 16));
    }
#pragma unroll
    for (int np = 0; np < 2; np++) {
        int row = n0 + np*16 + (lane & 7) + ((lane >> 4) << 3);
        boff[np] = SW128((uint32_t)(row * 128 + ((lane >> 3) & 1) * 16));
    }

    stage_tile(sb, aH, aL, bH, bL, DD, DD, 0, tid);
    CP_COMMIT;

    for (int kc = 0; kc < 4; kc++) {
        if (kc + 1 < 4) {
            stage_tile(sb + ((kc + 1) & 1) * BUFSZ, aH, aL, bH, bL, DD, DD, kc + 1, tid);
            CP_COMMIT;
            CP_WAIT1;
        } else {
            CP_WAIT0;
        }
        __syncthreads();

        uint32_t sbuf = sb + (kc & 1) * BUFSZ;
#pragma unroll
        for (int ks = 0; ks < 4; ks++) {
            uint32_t kb = ks * 32;
            uint32_t ah[2][4], al[2][4], bh[2][4], bl[2][4];
#pragma unroll
            for (int mi = 0; mi < 2; mi++) {
                ldm_x4(ah[mi], sbuf + SM_AH + (aoff[mi] ^ kb));
                ldm_x4(al[mi], sbuf + SM_AL + (aoff[mi] ^ kb));
            }
#pragma unroll
            for (int np = 0; np < 2; np++) {
                ldm_x4(bh[np], sbuf + SM_BH + (boff[np] ^ kb));
                ldm_x4(bl[np], sbuf + SM_BL + (boff[np] ^ kb));
            }
#pragma unroll
            for (int mi = 0; mi < 2; mi++)
#pragma unroll
                for (int ni = 0; ni < 4; ni++) {
                    const uint32_t* bph = &bh[ni >> 1][(ni & 1) * 2];
                    const uint32_t* bpl = &bl[ni >> 1][(ni & 1) * 2];
                    mma_bf16(acc[mi][ni], ah[mi], bph);
                    mma_bf16(acc[mi][ni], ah[mi], bpl);
                    mma_bf16(acc[mi][ni], al[mi], bph);
                }
        }
        __syncthreads();
    }

#pragma unroll
    for (int mi = 0; mi < 2; mi++)
#pragma unroll
        for (int ni = 0; ni < 4; ni++) {
            int l = lt * 128 + m0 + mi * 16 + (lane >> 2);
            int j = jt * 64 + n0 + ni * 8 + (lane & 3) * 2;
#pragma unroll
            for (int h = 0; h < 2; h++) {
                size_t o = ((size_t)(b * LL + l + h * 8)) * DD + j;
                *reinterpret_cast<float2*>(&g_w[o]) =
                    make_float2(acc[mi][ni][h*2], acc[mi][ni][h*2+1]);
            }
        }
}

// ======================= K3: output epilogue v3 =============================
// 8-lane groups (warp = 4 rows, lane = 32 contiguous d). d-chunks OUTER,
// p INNER, 60 independent fp32 partial accumulators; all shuffles batched
// at the end (no serialized reduction chains in the hot loop).
__global__ __launch_bounds__(256) void k_out(const float* __restrict__ ker,
                                             float* __restrict__ out) {
    __shared__ float ksq[PP * 288];     // [p][seg][36]
    __shared__ float vsm[8 * 36];       // [seg][36]
    int tid = threadIdx.x;
    int wid = tid >> 5, lane = tid & 31;
    int g = lane >> 3, sub = lane & 7;
    int row0 = blockIdx.x * 32;
    int b = blockIdx.x >> 5;
    int row = row0 + wid * 4 + g;

    for (int i = tid; i < PP * DD; i += 256) {
        int p = i >> 8, d = i & 255;
        float t = ker[i];
        ksq[p * 288 + (d >> 5) * 36 + (d & 31)] = t * t;
    }
    vsm[(tid >> 5) * 36 + (tid & 31)] = g_v[b * DD + tid];
    __syncthreads();

    const uint4*  xh = reinterpret_cast<const uint4*>(g_x1h + (size_t)row * DD + sub * 32);
    const uint4*  xl = reinterpret_cast<const uint4*>(g_x1l + (size_t)row * DD + sub * 32);
    const float4* wp = reinterpret_cast<const float4*>(g_w + (size_t)row * DD + sub * 32);
    const float*  vp = &vsm[sub * 36];

    float ps[PP][3];
#pragma unroll
    for (int p = 0; p < PP; p++) { ps[p][0] = 0.f; ps[p][1] = 0.f; ps[p][2] = 0.f; }
    float rsp = 0.f;

#pragma unroll
    for (int c = 0; c < 4; c++) {           // chunks of 8 d
        uint4 H = xh[c], L = xl[c];
        float s[8];
        uint32_t hu[4] = {H.x, H.y, H.z, H.w};
        uint32_t lu[4] = {L.x, L.y, L.z, L.w};
#pragma unroll
        for (int k = 0; k < 4; k++) {
            s[2*k]   = __uint_as_float(hu[k] << 16) + __uint_as_float(lu[k] << 16);
            s[2*k+1] = __uint_as_float(hu[k] & 0xFFFF0000u) + __uint_as_float(lu[k] & 0xFFFF0000u);
        }
        float4 Wa = wp[c*2], Wb = wp[c*2+1];
        float wv[8] = {Wa.x, Wa.y, Wa.z, Wa.w, Wb.x, Wb.y, Wb.z, Wb.w};
#pragma unroll
        for (int k = 0; k < 8; k++) rsp += s[k] * vp[c*8 + k];

        unsigned long long u2[4], q2[4], w2[4];
#pragma unroll
        for (int k = 0; k < 4; k++) {
            u2[k] = pack2(s[2*k]*wv[2*k],  s[2*k+1]*wv[2*k+1]);
            q2[k] = pack2(s[2*k]*s[2*k],   s[2*k+1]*s[2*k+1]);
            w2[k] = pack2(wv[2*k]*wv[2*k], wv[2*k+1]*wv[2*k+1]);
        }

#pragma unroll 5
        for (int p = 0; p < PP; p++) {
            const ulonglong2* kp =
                reinterpret_cast<const ulonglong2*>(&ksq[p * 288 + sub * 36 + c * 8]);
            ulonglong2 K0 = kp[0], K1 = kp[1];   // 8 kk values as 4 pairs
            unsigned long long a1 = 0ull, a2 = 0ull, a3 = 0ull;
            FMA2(a1, K0.x, u2[0]); FMA2(a1, K0.y, u2[1]);
            FMA2(a1, K1.x, u2[2]); FMA2(a1, K1.y, u2[3]);
            FMA2(a2, K0.x, q2[0]); FMA2(a2, K0.y, q2[1]);
            FMA2(a2, K1.x, q2[2]); FMA2(a2, K1.y, q2[3]);
            FMA2(a3, K0.x, w2[0]); FMA2(a3, K0.y, w2[1]);
            FMA2(a3, K1.x, w2[2]); FMA2(a3, K1.y, w2[3]);
            ps[p][0] += lo32(a1) + hi32(a1);
            ps[p][1] += lo32(a2) + hi32(a2);
            ps[p][2] += lo32(a3) + hi32(a3);
        }
    }

    // ---- batched reductions: 61 independent butterfly chains ----
#pragma unroll
    for (int o = 4; o; o >>= 1) rsp += __shfl_xor_sync(0xffffffffu, rsp, o);
#pragma unroll
    for (int p = 0; p < PP; p++)
#pragma unroll
        for (int q = 0; q < 3; q++)
#pragma unroll
            for (int o = 4; o; o >>= 1)
                ps[p][q] += __shfl_xor_sync(0xffffffffu, ps[p][q], o);

    float invd = 1.0f / (rsp + EPS);
    float invd2 = invd * invd;

    // lane sub writes p = sub, sub+8, sub+16
    float* orow = out + (size_t)row * PP;
#pragma unroll
    for (int t = 0; t < 3; t++) {
        int p = sub + t * 8;
        if (p < PP) {
            float val = (ps[p][0] * invd) * rsqrtf(fmaxf(ps[p][1], EPS))
                                          * rsqrtf(fmaxf(ps[p][2] * invd2, EPS));
            orow[p] = val;
        }
    }
}

// ======================= launch =======================
extern "C" void kernel_launch(void* const* d_in, const int* in_sizes, int n_in,
                              void* d_out, int out_size) {
    const float* s1  = (const float*)d_in[0];   // [16,1024,256]
    const float* s2  = (const float*)d_in[1];   // [16,1024,256]
    const float* ker = (const float*)d_in[2];   // [20,256]
    float* out = (float*)d_out;                 // [16,1024,20]

    cudaFuncSetAttribute(k_gramv,  cudaFuncAttributeMaxDynamicSharedMemorySize, 2*BUFSZ);
    cudaFuncSetAttribute(k_wt_mma, cudaFuncAttributeMaxDynamicSharedMemorySize, 2*BUFSZ);

    k_pt<<<2560, 256>>>(s1, s2);
    k_gramv<<<144, 256, 2*BUFSZ>>>();
    k_wt_mma<<<dim3(16, 8, 4), 256, 2*BUFSZ>>>();
    k_out<<<512, 256>>>(ker, out);
}